// round 7
// baseline (speedup 1.0000x reference)
#include <cuda_runtime.h>

#define B_   16
#define N_   1024
#define H_   224
#define W_   224
#define W2   112              // W_/2
#define W4   56               // W_/4
#define KS   23
#define HALF 11
#define SIGMA2X2 18.0f        // 2 * 3.0^2
#define RPB  32               // output rows per block
#define TILES_Y (H_ / RPB)    // 7
#define STRIP (RPB + KS - 1)  // 54 hist rows per strip
#define RT   4                // y-conv rows per unit -> (32/4)*112 = 896 units (float2)
#define XT   7                // x-conv cols per unit -> 32 tiles * 32 rows = 1024 units
#define XTILES (W_ / XT)      // 32
#define NTHR 1024
#define NBLK (B_ * TILES_Y)   // 112 blocks — one per SM, single wave

#define HIST_F (STRIP * W_)   // 12096 floats
#define BW     256            // padded B row: [0..10]=0 halo, [11..234]=data, rest 0
#define B_F    (RPB * BW)     // 8192 floats
#define SMEM_BYTES ((HIST_F + B_F) * (int)sizeof(float))  // 81152 B

__global__ void __launch_bounds__(NTHR, 1)
saliency_hist_kernel(const float* __restrict__ points, float* __restrict__ out) {
    extern __shared__ float smem[];
    float* s_hist = smem;            // [STRIP][W_]   point-count histogram
    float* s_B    = smem + HIST_F;   // [RPB][BW]     y-convolved, zero-padded halo
    __shared__ float s_w[KS];

    const int tidx = threadIdx.x;
    const int b    = blockIdx.x / TILES_Y;
    const int tile = blockIdx.x % TILES_Y;
    const int r0   = tile * RPB;
    const int ylo  = r0 - HALF;      // hist row 0 == global row ylo

    // ---- Phase 0: zero hist + B (incl. halos) + normalized 1-D Gaussian ----
    {
        float4 z = make_float4(0.f, 0.f, 0.f, 0.f);
        float4* s4 = reinterpret_cast<float4*>(smem);
        #pragma unroll
        for (int k = tidx; k < (HIST_F + B_F) / 4; k += NTHR)   // 5072 float4s
            s4[k] = z;
    }
    if (tidx < 32) {
        float d = (float)tidx - (float)(KS - 1) * 0.5f;
        float v = (tidx < KS) ? expf(-(d * d) / SIGMA2X2) : 0.0f;
        float s = v;
        #pragma unroll
        for (int off = 16; off > 0; off >>= 1)
            s += __shfl_xor_sync(0xFFFFFFFFu, s, off);
        if (tidx < KS) s_w[tidx] = v / s;
    }
    __syncthreads();

    // ---- Phase 1: histogram scatter — one smem atomic per matching point ----
    if (tidx < N_) {
        float2 p = reinterpret_cast<const float2*>(points)[b * N_ + tidx];
        int x = (int)(p.x * (float)W_);   // truncation == astype(int32), nonneg
        int y = (int)(p.y * (float)H_);
        int u = y - ylo;
        if ((unsigned)u < (unsigned)STRIP &&
            (unsigned)x < (unsigned)W_ && (unsigned)y < (unsigned)H_)
            atomicAdd(&s_hist[u * W_ + x], 1.0f);
    }
    __syncthreads();

    // ---- Phase 2: dense y-conv (float2 columns)  B[rl][11+c] = sum_j w[j]*hist[rl+j][c]
    if (tidx < (RPB / RT) * W2) {             // 896 units
        int c2  = tidx % W2;
        int rl0 = (tidx / W2) * RT;

        float w[KS];
        #pragma unroll
        for (int j = 0; j < KS; j++) w[j] = s_w[j];

        float2 acc[RT];
        #pragma unroll
        for (int k = 0; k < RT; k++) acc[k] = make_float2(0.f, 0.f);

        const float2* hc = reinterpret_cast<const float2*>(s_hist) + c2;
        #pragma unroll
        for (int u = 0; u < RT + KS - 1; u++) {   // 26 strip rows
            float2 v = hc[(rl0 + u) * W2];
            #pragma unroll
            for (int k = 0; k < RT; k++) {
                int j = u - k;                    // compile-time per (u,k)
                if (j >= 0 && j < KS) {
                    acc[k].x = fmaf(w[j], v.x, acc[k].x);
                    acc[k].y = fmaf(w[j], v.y, acc[k].y);
                }
            }
        }
        // store into padded B at column offset HALF
        #pragma unroll
        for (int k = 0; k < RT; k++) {
            float* dst = s_B + (rl0 + k) * BW + HALF + c2 * 2;
            dst[0] = acc[k].x;
            dst[1] = acc[k].y;
        }
    }
    __syncthreads();

    // ---- Phase 3: dense x-conv, no guards (halo), conflict-free (stride 7) ----
    {
        float w[KS];
        #pragma unroll
        for (int j = 0; j < KS; j++) w[j] = s_w[j];

        int ct = tidx % XTILES;               // lane == ct -> distinct banks
        int r  = tidx / XTILES;
        int c0 = ct * XT;

        float acc[XT];
        #pragma unroll
        for (int k = 0; k < XT; k++) acc[k] = 0.f;

        // padded index: data col cc -> s_B[r][cc + HALF]; window starts at c0
        const float* brow = s_B + r * BW + c0;
        #pragma unroll
        for (int u = 0; u < XT + KS - 1; u++) {   // 29 taps window
            float v = brow[u];
            #pragma unroll
            for (int k = 0; k < XT; k++) {
                int j = u - k;
                if (j >= 0 && j < KS)
                    acc[k] = fmaf(w[j], v, acc[k]);
            }
        }

        float* orow = out + (b * H_ + r0 + r) * W_ + c0;
        #pragma unroll
        for (int k = 0; k < XT; k++)
            orow[k] = acc[k];
    }
}

extern "C" void kernel_launch(void* const* d_in, const int* in_sizes, int n_in,
                              void* d_out, int out_size) {
    const float* points = (const float*)d_in[1];  // d_in[0] = feature_map (unused)
    float* out = (float*)d_out;
    cudaFuncSetAttribute(saliency_hist_kernel,
                         cudaFuncAttributeMaxDynamicSharedMemorySize, SMEM_BYTES);
    saliency_hist_kernel<<<NBLK, NTHR, SMEM_BYTES>>>(points, out);
}

// round 8
// speedup vs baseline: 1.0239x; 1.0239x over previous
#include <cuda_runtime.h>
#include <cstdint>

#define B_   16
#define N_   1024
#define H_   224
#define W_   224
#define W2   112              // W_/2
#define KS   23
#define HALF 11
#define SIGMA2X2 18.0f        // 2 * 3.0^2
#define RPB  14               // output rows per block
#define TILES_Y (H_ / RPB)    // 16
#define STRIP (RPB + KS - 1)  // 36 hist rows per strip
#define RT   2                // y-conv rows per unit -> 7*112 = 784 units (float2)
#define XT   7                // x-conv cols per unit -> 32 tiles * 14 rows = 448 units
#define XTILES (W_ / XT)      // 32
#define NTHR 512
#define NBLK (B_ * TILES_Y)   // 256 blocks, 2 per SM co-resident

#define HIST_F (STRIP * W_)   // 8064 floats (32256 B)
#define BW     256            // padded B row: [0..10]=0 halo, [11..234]=data, rest 0
#define B_F    (RPB * BW)     // 3584 floats (14336 B)
// total static smem: 46592 B + weights < 48K default limit

__device__ __forceinline__ void ffma2(unsigned long long& acc,
                                      unsigned long long w2,
                                      unsigned long long v2) {
    asm("fma.rn.f32x2 %0, %1, %2, %0;" : "+l"(acc) : "l"(w2), "l"(v2));
}

__global__ void __launch_bounds__(NTHR, 2)
saliency_hist_kernel(const float* __restrict__ points, float* __restrict__ out) {
    __shared__ float s_hist[HIST_F];              // [STRIP][W_] histogram
    __shared__ float s_B[B_F];                    // [RPB][BW]  y-convolved (padded)
    __shared__ float s_w[KS];                     // scalar weights
    __shared__ unsigned long long s_w2[KS];       // packed {w,w}

    const int tidx = threadIdx.x;
    const int b    = blockIdx.x / TILES_Y;
    const int tile = blockIdx.x % TILES_Y;
    const int r0   = tile * RPB;
    const int ylo  = r0 - HALF;                   // hist row 0 == global row ylo

    // ---- Prefetch this thread's 2 points (overlaps smem zeroing) ----
    const float2* pts = reinterpret_cast<const float2*>(points) + b * N_;
    float2 p0 = pts[tidx];
    float2 p1 = pts[tidx + NTHR];

    // ---- Phase 0: zero hist + B, compute Gaussian (scalar + packed) ----
    {
        float4 z = make_float4(0.f, 0.f, 0.f, 0.f);
        float4* h4 = reinterpret_cast<float4*>(s_hist);
        #pragma unroll
        for (int k = tidx; k < HIST_F / 4; k += NTHR) h4[k] = z;
        float4* b4 = reinterpret_cast<float4*>(s_B);
        #pragma unroll
        for (int k = tidx; k < B_F / 4; k += NTHR) b4[k] = z;
    }
    if (tidx < 32) {
        float d = (float)tidx - (float)(KS - 1) * 0.5f;
        float v = (tidx < KS) ? expf(-(d * d) / SIGMA2X2) : 0.0f;
        float s = v;
        #pragma unroll
        for (int off = 16; off > 0; off >>= 1)
            s += __shfl_xor_sync(0xFFFFFFFFu, s, off);
        if (tidx < KS) {
            float wj = v / s;
            s_w[tidx] = wj;
            unsigned long long w2;
            asm("mov.b64 %0, {%1, %1};" : "=l"(w2) : "r"(__float_as_uint(wj)));
            s_w2[tidx] = w2;
        }
    }
    __syncthreads();

    // ---- Phase 1: histogram scatter — one smem atomic per matching point ----
    {
        int x0 = (int)(p0.x * (float)W_), y0 = (int)(p0.y * (float)H_);
        int u0 = y0 - ylo;
        if ((unsigned)u0 < (unsigned)STRIP &&
            (unsigned)x0 < (unsigned)W_ && (unsigned)y0 < (unsigned)H_)
            atomicAdd(&s_hist[u0 * W_ + x0], 1.0f);
        int x1 = (int)(p1.x * (float)W_), y1 = (int)(p1.y * (float)H_);
        int u1 = y1 - ylo;
        if ((unsigned)u1 < (unsigned)STRIP &&
            (unsigned)x1 < (unsigned)W_ && (unsigned)y1 < (unsigned)H_)
            atomicAdd(&s_hist[u1 * W_ + x1], 1.0f);
    }
    __syncthreads();

    // ---- Phase 2: dense y-conv, float2 columns, packed FFMA2 ----
    // B[rl][HALF+2c..] = sum_j w[j] * hist[rl+j][2c..]; rolling weight window.
    {
        const unsigned long long* h2 =
            reinterpret_cast<const unsigned long long*>(s_hist);
        #pragma unroll
        for (int unit = tidx; unit < (RPB / RT) * W2; unit += NTHR) {  // 784 units
            int c2  = unit % W2;
            int rl0 = (unit / W2) * RT;

            unsigned long long acc0 = 0ull, acc1 = 0ull;
            unsigned long long wcur = 0ull, wprev;
            #pragma unroll
            for (int u = 0; u < RT + KS - 1; u++) {   // 24 strip rows
                unsigned long long v2 = h2[(rl0 + u) * W2 + c2];
                wprev = wcur;
                if (u < KS) wcur = s_w2[u];           // LDS.64 broadcast
                if (u < KS)  ffma2(acc0, wcur, v2);   // k=0: j=u
                if (u >= 1)  ffma2(acc1, wprev, v2);  // k=1: j=u-1
            }
            float2 a0 = *reinterpret_cast<float2*>(&acc0);
            float2 a1 = *reinterpret_cast<float2*>(&acc1);
            float* d0 = s_B + (rl0 + 0) * BW + HALF + c2 * 2;
            float* d1 = s_B + (rl0 + 1) * BW + HALF + c2 * 2;
            d0[0] = a0.x; d0[1] = a0.y;
            d1[0] = a1.x; d1[1] = a1.y;
        }
    }
    __syncthreads();

    // ---- Phase 3: dense x-conv, halo-padded (no guards), stride-7 conflict-free
    if (tidx < RPB * XTILES) {                    // 448 units
        int ct = tidx % XTILES;                   // lane == ct -> distinct banks
        int r  = tidx / XTILES;
        int c0 = ct * XT;

        float acc[XT];
        #pragma unroll
        for (int k = 0; k < XT; k++) acc[k] = 0.f;

        float wr[XT];                             // rolling weight window
        #pragma unroll
        for (int k = 0; k < XT; k++) wr[k] = 0.f;

        const float* brow = s_B + r * BW + c0;    // data col cc at brow[cc-c0+HALF-HALF]
        #pragma unroll
        for (int u = 0; u < XT + KS - 1; u++) {   // 29 taps window
            // shift window: wr[k] holds w[u-k] after this step
            #pragma unroll
            for (int k = XT - 1; k >= 1; k--) wr[k] = wr[k - 1];
            wr[0] = (u < KS) ? s_w[u] : 0.f;      // LDS broadcast

            float v = brow[u];
            #pragma unroll
            for (int k = 0; k < XT; k++)
                acc[k] = fmaf(wr[k], v, acc[k]);
        }

        float* orow = out + (b * H_ + r0 + r) * W_ + c0;
        #pragma unroll
        for (int k = 0; k < XT; k++)
            orow[k] = acc[k];
    }
}

extern "C" void kernel_launch(void* const* d_in, const int* in_sizes, int n_in,
                              void* d_out, int out_size) {
    const float* points = (const float*)d_in[1];  // d_in[0] = feature_map (unused)
    float* out = (float*)d_out;
    saliency_hist_kernel<<<NBLK, NTHR>>>(points, out);
}

// round 10
// speedup vs baseline: 1.2704x; 1.2407x over previous
#include <cuda_runtime.h>

#define B_   16
#define N_   1024
#define H_   224
#define W_   224
#define W2   112              // W_/2
#define KS   23
#define HALF 11
#define SIGMA2X2 18.0f        // 2 * 3.0^2
#define RPB  14               // output rows per block
#define TILES_Y 16            // H_/RPB
#define STRIP 36              // RPB+KS-1 hist rows
#define NTHR 256
#define NBLK (B_ * TILES_Y)   // 256 blocks

#define HIST_F (STRIP * W_)   // 8064 floats
#define BW     247            // odd row stride; 247%32=23 coprime -> conflict-free
#define B_F    (RPB * BW)     // 3458 floats
#define YRT    7              // y-conv rows per unit
#define YUNITS (2 * W2)       // 224 units (float2 cols x 2 row-groups)
#define XT     8              // x-conv cols per unit (4 packed pairs)
#define XTILES (W_ / XT)      // 28
#define XUNITS (RPB * XTILES) // 392

typedef unsigned long long u64;

__device__ __forceinline__ void ffma2(u64& acc, u64 a, u64 b) {
    asm("fma.rn.f32x2 %0, %1, %2, %0;" : "+l"(acc) : "l"(a), "l"(b));
}
__device__ __forceinline__ u64 pack2(float lo, float hi) {
    u64 r;
    asm("mov.b64 %0, {%1, %2};"
        : "=l"(r) : "r"(__float_as_uint(lo)), "r"(__float_as_uint(hi)));
    return r;
}
__device__ __forceinline__ float2 unpack2(u64 v) {
    float2 r;
    asm("mov.b64 {%0, %1}, %2;" : "=f"(r.x), "=f"(r.y) : "l"(v));
    return r;
}

__global__ void __launch_bounds__(NTHR, 4)
saliency_kernel(const float* __restrict__ points, float* __restrict__ out) {
    __shared__ __align__(16) float s_hist[HIST_F];  // [STRIP][W_]
    __shared__ __align__(16) float s_B[B_F];        // [RPB][BW], cols [0..10] halo=0
    __shared__ float s_w[KS];
    __shared__ u64   s_w2[KS];   // {w[j], w[j]}
    __shared__ u64   s_wp[KS+1]; // {w[u], w[u-1]}, u in 0..23 (edges zero-padded)

    const int tidx = threadIdx.x;
    const int b    = blockIdx.x / TILES_Y;
    const int tile = blockIdx.x % TILES_Y;
    const int r0   = tile * RPB;
    const int ylo  = r0 - HALF;                     // hist row 0 == global row ylo

    // ---- Prefetch this thread's 4 points (2 float4 = 4 (x,y) pairs) ----
    const float4* p4 = reinterpret_cast<const float4*>(points + b * N_ * 2);
    float4 pa = p4[tidx];
    float4 pb = p4[tidx + NTHR];

    // ---- Phase 0: zero hist + B, build weight tables ----
    {
        float4 z4 = make_float4(0.f, 0.f, 0.f, 0.f);
        float4* h4 = reinterpret_cast<float4*>(s_hist);
        #pragma unroll
        for (int k = tidx; k < HIST_F / 4; k += NTHR) h4[k] = z4;
        float2 z2 = make_float2(0.f, 0.f);
        float2* b2 = reinterpret_cast<float2*>(s_B);
        #pragma unroll
        for (int k = tidx; k < B_F / 2; k += NTHR) b2[k] = z2;
    }
    if (tidx < 32) {
        float d = (float)tidx - (float)(KS - 1) * 0.5f;
        float v = (tidx < KS) ? expf(-(d * d) / SIGMA2X2) : 0.0f;
        float s = v;
        #pragma unroll
        for (int off = 16; off > 0; off >>= 1)
            s += __shfl_xor_sync(0xFFFFFFFFu, s, off);
        if (tidx < KS) s_w[tidx] = v / s;
        __syncwarp();
        if (tidx < KS) s_w2[tidx] = pack2(s_w[tidx], s_w[tidx]);
        if (tidx <= KS) {
            float lo = (tidx < KS) ? s_w[tidx] : 0.f;
            float hi = (tidx >= 1) ? s_w[tidx - 1] : 0.f;
            s_wp[tidx] = pack2(lo, hi);
        }
    }
    __syncthreads();

    // ---- Phase 1: histogram scatter — one smem atomic per matching point ----
    {
        #pragma unroll
        for (int q = 0; q < 4; q++) {
            float px = (q == 0) ? pa.x : (q == 1) ? pa.z : (q == 2) ? pb.x : pb.z;
            float py = (q == 0) ? pa.y : (q == 1) ? pa.w : (q == 2) ? pb.y : pb.w;
            int x = (int)(px * (float)W_);  // truncation == astype(int32), nonneg
            int y = (int)(py * (float)H_);
            int u = y - ylo;
            if ((unsigned)u < (unsigned)STRIP &&
                (unsigned)x < (unsigned)W_ && (unsigned)y < (unsigned)H_)
                atomicAdd(&s_hist[u * W_ + x], 1.0f);
        }
    }
    __syncthreads();

    // ---- Phase 2: y-conv, float2 cols, 7-row register tile, FFMA2 ----
    // B[rl][HALF+2c..] = sum_j w[j] * hist[rl+j][2c..]
    if (tidx < YUNITS) {
        int c2  = tidx % W2;
        int rl0 = (tidx / W2) * YRT;

        const u64* h2 = reinterpret_cast<const u64*>(s_hist);
        u64 acc[YRT];
        #pragma unroll
        for (int k = 0; k < YRT; k++) acc[k] = 0ull;
        u64 wv[YRT];
        #pragma unroll
        for (int k = 0; k < YRT; k++) wv[k] = 0ull;

        #pragma unroll
        for (int u = 0; u < YRT + KS - 1; u++) {  // 29 strip rows
            #pragma unroll
            for (int k = YRT - 1; k >= 1; k--) wv[k] = wv[k - 1];  // renamed
            if (u < KS) wv[0] = s_w2[u];                           // broadcast
            u64 v2 = h2[(rl0 + u) * W2 + c2];
            #pragma unroll
            for (int k = 0; k < YRT; k++) {
                int j = u - k;
                if (j >= 0 && j < KS) ffma2(acc[k], wv[k], v2);
            }
        }
        #pragma unroll
        for (int k = 0; k < YRT; k++) {
            float2 a = unpack2(acc[k]);
            float* dst = s_B + (rl0 + k) * BW + HALF + c2 * 2;
            dst[0] = a.x;
            dst[1] = a.y;
        }
    }
    __syncthreads();

    // ---- Phase 3: x-conv, packed output pairs (FFMA2), halo-padded ----
    // acc[k] = {out[c0+2k], out[c0+2k+1]}; shared input v, pair weights s_wp[u-2k]
    #pragma unroll
    for (int it = 0; it < 2; it++) {
        int unit = tidx + it * NTHR;
        if (unit < XUNITS) {
            int r  = unit % RPB;         // row-major: lane stride = BW (coprime 32)
            int ct = unit / RPB;
            int c0 = ct * XT;

            const float* brow = s_B + r * BW + c0;  // brow[u] == input col c0+u-11
            u64 acc[XT / 2];
            #pragma unroll
            for (int k = 0; k < XT / 2; k++) acc[k] = 0ull;
            u64 wv[XT - 1];
            #pragma unroll
            for (int k = 0; k < XT - 1; k++) wv[k] = 0ull;

            #pragma unroll
            for (int u = 0; u < XT + KS - 1; u++) {   // 30 taps window
                #pragma unroll
                for (int k = XT - 2; k >= 1; k--) wv[k] = wv[k - 1];
                if (u <= KS) wv[0] = s_wp[u];          // broadcast, 24 entries
                float v = brow[u];
                u64 vv = pack2(v, v);
                #pragma unroll
                for (int k = 0; k < XT / 2; k++) {
                    int up = u - 2 * k;                // wv[2k] == s_wp[u-2k]
                    if (up >= 0 && up <= KS) ffma2(acc[k], wv[2 * k], vv);
                }
            }

            float2 a0 = unpack2(acc[0]);
            float2 a1 = unpack2(acc[1]);
            float2 a2 = unpack2(acc[2]);
            float2 a3 = unpack2(acc[3]);
            float* orow = out + (b * H_ + r0 + r) * W_ + c0;
            reinterpret_cast<float4*>(orow)[0] = make_float4(a0.x, a0.y, a1.x, a1.y);
            reinterpret_cast<float4*>(orow)[1] = make_float4(a2.x, a2.y, a3.x, a3.y);
        }
    }
}

extern "C" void kernel_launch(void* const* d_in, const int* in_sizes, int n_in,
                              void* d_out, int out_size) {
    const float* points = (const float*)d_in[1];  // d_in[0] = feature_map (unused)
    float* out = (float*)d_out;
    saliency_kernel<<<NBLK, NTHR>>>(points, out);
}